// round 14
// baseline (speedup 1.0000x reference)
#include <cuda_runtime.h>
#include <cuda_fp16.h>
#include <cstdint>
#include <cstddef>

// Problem constants
#define Hh   1024
#define Bb   16384
#define Ss   8
#define NW   6144          // [op1 | num1 | gates interleaved 4*j+g]
#define KTOT 1024
#define NCHUNK 16          // KTOT / 64

#define BM 128
#define BN 128
#define STAGES      3
#define STAGE_BYTES 32768  // A 128x64 fp16 (16KB) + B 128x64 fp16 (16KB)
#define SMEM_TOT    (STAGES * STAGE_BYTES)
#define NTHREADS    256

// ---------------------------------------------------------------------------
// Device scratch
// ---------------------------------------------------------------------------
__device__ __half  g_W2[(size_t)NW * KTOT];      // 12.6 MB packed fp16 weights
__device__ __half  g_A2[2][(size_t)Bb * KTOT];   // ping-pong fp16 activations
__device__ float   g_Wop2t[5 * Hh];              // transposed op head weights
__device__ float   g_hb[2 * Hh];                 // [b_op1 | b_num1]
__device__ float   g_gb[4 * Hh];                 // interleaved gate biases

// ---------------------------------------------------------------------------
// Helpers
// ---------------------------------------------------------------------------
__device__ __forceinline__ float gelu_exact(float x) {
    return 0.5f * x * (1.0f + erff(x * 0.70710678118654752f));
}
__device__ __forceinline__ float fast_sig(float x) {
    return __fdividef(1.0f, 1.0f + __expf(-x));
}
__device__ __forceinline__ float fast_tanh(float x) {
    return __fdividef(2.0f, 1.0f + __expf(-2.0f * x)) - 1.0f;
}
__device__ __forceinline__ uint32_t smem_u32(const void* p) {
    uint32_t a;
    asm("{ .reg .u64 t; cvta.to.shared.u64 t, %1; cvt.u32.u64 %0, t; }" : "=r"(a) : "l"(p));
    return a;
}
__device__ __forceinline__ void cpasync16(uint32_t dst, const void* src) {
    asm volatile("cp.async.cg.shared.global [%0], [%1], 16;" :: "r"(dst), "l"(src) : "memory");
}
__device__ __forceinline__ void cp_commit() {
    asm volatile("cp.async.commit_group;" ::: "memory");
}
template <int N>
__device__ __forceinline__ void cp_wait() {
    asm volatile("cp.async.wait_group %0;" :: "n"(N) : "memory");
}
__device__ __forceinline__ void ldsm4(uint32_t* r, uint32_t addr) {
    asm volatile("ldmatrix.sync.aligned.m8n8.x4.shared.b16 {%0,%1,%2,%3}, [%4];"
                 : "=r"(r[0]), "=r"(r[1]), "=r"(r[2]), "=r"(r[3]) : "r"(addr));
}
// fp16-accumulate HMMA: D(f16x2 x2) = A*B + C
__device__ __forceinline__ void mma_f16acc(uint32_t* c, const uint32_t* a, const uint32_t* b) {
    asm volatile(
        "mma.sync.aligned.m16n8k16.row.col.f16.f16.f16.f16 "
        "{%0,%1}, {%2,%3,%4,%5}, {%6,%7}, {%0,%1};"
        : "+r"(c[0]), "+r"(c[1])
        : "r"(a[0]), "r"(a[1]), "r"(a[2]), "r"(a[3]), "r"(b[0]), "r"(b[1]));
}
__device__ __forceinline__ uint32_t sw128(uint32_t off) {
    return off ^ ((off >> 3) & 0x70);
}

// ---------------------------------------------------------------------------
// Pack fp16 weights, gate-interleaved
// ---------------------------------------------------------------------------
__global__ void pack_w2(const float* __restrict__ w_op1, const float* __restrict__ w_num1,
                        const float* __restrict__ w_ih, const float* __restrict__ w_hh) {
    size_t idx = (size_t)blockIdx.x * 256 + threadIdx.x;   // over NW*1024
    int n = (int)(idx >> 10);
    int kk = (int)(idx & 1023);
    float v;
    if (n < 1024)      v = w_op1[(size_t)kk * Hh + n];
    else if (n < 2048) v = w_num1[(size_t)kk * Hh + (n - 1024)];
    else {
        int j = (n - 2048) >> 2;
        int g = n & 3;
        if (g == 0)      v = w_ih[(size_t)j * Hh + kk] + w_hh[(size_t)j * Hh + kk];
        else if (g == 1) v = w_ih[(size_t)(1024 + j) * Hh + kk] + w_hh[(size_t)(1024 + j) * Hh + kk];
        else if (g == 2) v = w_ih[(size_t)(2048 + j) * Hh + kk];
        else             v = w_hh[(size_t)(2048 + j) * Hh + kk];
    }
    g_W2[idx] = __float2half_rn(v);
}

__global__ void pack_misc(const float* __restrict__ w_op2,
                          const float* __restrict__ b_op1, const float* __restrict__ b_num1,
                          const float* __restrict__ b_ih, const float* __restrict__ b_hh) {
    int idx = blockIdx.x * 256 + threadIdx.x;   // 0..11263
    if (idx < 5120) {
        int q = idx >> 10, c = idx & 1023;
        g_Wop2t[idx] = w_op2[(size_t)c * 5 + q];
    } else if (idx < 5120 + 2048) {
        int c = idx - 5120;
        g_hb[c] = (c < 1024) ? b_op1[c] : b_num1[c - 1024];
    } else if (idx < 5120 + 2048 + 4096) {
        int c = idx - 5120 - 2048;
        int j = c >> 2, g = c & 3;
        float v;
        if (g == 0)      v = b_ih[j] + b_hh[j];
        else if (g == 1) v = b_ih[1024 + j] + b_hh[1024 + j];
        else if (g == 2) v = b_ih[2048 + j];
        else             v = b_hh[2048 + j];
        g_gb[c] = v;
    }
}

__global__ void convert_x(const float* __restrict__ x, float* __restrict__ states0) {
    size_t idx = (size_t)blockIdx.x * 256 + threadIdx.x;
    float h = x[idx];
    states0[idx] = h;
    g_A2[0][idx] = __float2half_rn(h);
}

// init ALL steps' ops/nums with biases (one launch)
__global__ void init_heads_all(float* __restrict__ ops, float* __restrict__ nums,
                               const float* __restrict__ b_op2, const float* __restrict__ b_num2) {
    int idx = blockIdx.x * 256 + threadIdx.x;   // 0 .. 8*Bb*6-1
    int tot_ops = Ss * Bb * 5;
    if (idx < tot_ops) ops[idx] = b_op2[idx % 5];
    else if (idx < tot_ops + Ss * Bb) nums[idx - tot_ops] = b_num2[0];
}

// ---------------------------------------------------------------------------
// Fused HMMA GEMM (fp16 accum per chunk, fp32 promotion) + heads/GRU epilogue.
// BM=128, BN=128, BK=64. 256 threads = 8 warps, warp tile 64x32.
// n-blocks: [0,8): op head; [8,16): num head; [16,48): gates.
// ---------------------------------------------------------------------------
__global__ void __launch_bounds__(NTHREADS, 1)
gemm_fused(const __half* __restrict__ Ain, __half* __restrict__ Aout,
           const float* __restrict__ h_in, float* __restrict__ h_out,
           const float* __restrict__ w_num2,
           float* __restrict__ ops, float* __restrict__ nums, int write_a2) {
    extern __shared__ char smem[];
    uint32_t sb = smem_u32(smem);
    int tid = threadIdx.x;
    int lane = tid & 31;
    int wid = tid >> 5;
    int n0 = blockIdx.x * BN;
    int m0 = blockIdx.y * BM;

    // ---- cp.async bases: 8 segs/thread (4 A + 4 B) ----
    int lrow = tid >> 3;            // 0..31
    int ls8 = tid & 7;
    uint32_t d0 = sw128((uint32_t)lrow * 128 + ls8 * 16);
    const char* pA0 = (const char*)(Ain + (size_t)(m0 + lrow) * KTOT) + ls8 * 16;
    const char* pB0 = (const char*)(g_W2 + (size_t)(n0 + lrow) * KTOT) + ls8 * 16;

    // ---- ldmatrix base offsets ----
    int wm = (wid >> 2) * 64;       // 0 or 64
    int wn = (wid & 3) * 32;        // 0..96
    uint32_t aoffb[4], boffb[2];
#pragma unroll
    for (int mi = 0; mi < 4; mi++)
        aoffb[mi] = sw128((uint32_t)(wm + mi * 16 + (lane & 15)) * 128 + ((lane >> 4) << 4));
#pragma unroll
    for (int nb = 0; nb < 2; nb++) {
        uint32_t rown = wn + nb * 16 + ((lane >> 4) & 1) * 8 + (lane & 7);
        boffb[nb] = sw128(rown * 128 + ((lane >> 3) & 1) * 16);
    }

    float cc[4][4][4];
#pragma unroll
    for (int mi = 0; mi < 4; mi++)
#pragma unroll
        for (int ni = 0; ni < 4; ni++)
#pragma unroll
            for (int q = 0; q < 4; q++) cc[mi][ni][q] = 0.0f;

    auto load_stage = [&](int st, int c) {
        uint32_t stb = sb + st * STAGE_BYTES;
        int kb = c * 128;
#pragma unroll
        for (int i = 0; i < 4; i++)
            cpasync16(stb + d0 + 4096 * i, pA0 + (size_t)i * 32 * (KTOT * 2) + kb);
#pragma unroll
        for (int i = 0; i < 4; i++)
            cpasync16(stb + 16384 + d0 + 4096 * i, pB0 + (size_t)i * 32 * (KTOT * 2) + kb);
    };

    load_stage(0, 0);
    cp_commit();
    load_stage(1, 1);
    cp_commit();

#pragma unroll 1
    for (int c = 0; c < NCHUNK; c++) {
        cp_wait<1>();
        __syncthreads();
        if (c + 2 < NCHUNK) load_stage((c + 2) % STAGES, c + 2);
        cp_commit();

        uint32_t stb = sb + (c % STAGES) * STAGE_BYTES;

        // fp16 chunk accumulators (zeroed per chunk; K=64 in fp16 is safe)
        uint32_t hc[4][4][2];
#pragma unroll
        for (int mi = 0; mi < 4; mi++)
#pragma unroll
            for (int ni = 0; ni < 4; ni++) {
                hc[mi][ni][0] = 0u;
                hc[mi][ni][1] = 0u;
            }

#pragma unroll
        for (int ks = 0; ks < 4; ks++) {
            uint32_t kx = (uint32_t)ks * 32;
            uint32_t a[4][4];
#pragma unroll
            for (int mi = 0; mi < 4; mi++) ldsm4(a[mi], stb + (aoffb[mi] ^ kx));
            uint32_t b[4][2];
#pragma unroll
            for (int nb = 0; nb < 2; nb++) {
                uint32_t r[4];
                ldsm4(r, stb + 16384 + (boffb[nb] ^ kx));
                b[nb * 2][0] = r[0]; b[nb * 2][1] = r[1];
                b[nb * 2 + 1][0] = r[2]; b[nb * 2 + 1][1] = r[3];
            }
#pragma unroll
            for (int mi = 0; mi < 4; mi++)
#pragma unroll
                for (int ni = 0; ni < 4; ni++)
                    mma_f16acc(hc[mi][ni], a[mi], b[ni]);
        }

        // promote chunk sums to fp32
#pragma unroll
        for (int mi = 0; mi < 4; mi++)
#pragma unroll
            for (int ni = 0; ni < 4; ni++) {
                float2 f0 = __half22float2(*(__half2*)&hc[mi][ni][0]);
                float2 f1 = __half22float2(*(__half2*)&hc[mi][ni][1]);
                cc[mi][ni][0] += f0.x;
                cc[mi][ni][1] += f0.y;
                cc[mi][ni][2] += f1.x;
                cc[mi][ni][3] += f1.y;
            }
    }

    // ---- fused epilogue ----
    int mrow = m0 + wm + (lane >> 2);
    int cbase = n0 + wn + (lane & 3) * 2;

    if (blockIdx.x >= 16) {
        // ======== gate CTAs: GRU combine ========
        int odd = lane & 1;
#pragma unroll
        for (int ni = 0; ni < 4; ni++) {
            int col = cbase + ni * 8;
            int j = (col - 2048) >> 2;
            float b0 = g_gb[col - 2048];
            float b1 = g_gb[col - 2048 + 1];
#pragma unroll
            for (int mi = 0; mi < 4; mi++) {
#pragma unroll
                for (int hf = 0; hf < 2; hf++) {
                    float v0 = cc[mi][ni][hf * 2 + 0] + b0;
                    float v1 = cc[mi][ni][hf * 2 + 1] + b1;
                    float u0 = __shfl_xor_sync(0xffffffffu, v0, 1);
                    float u1 = __shfl_xor_sync(0xffffffffu, v1, 1);
                    float pre_r = odd ? u0 : v0;
                    float pre_z = odd ? u1 : v1;
                    float i_n   = odd ? v0 : u0;
                    float h_n   = odd ? v1 : u1;
                    float r = fast_sig(pre_r);
                    float z = fast_sig(pre_z);
                    float nn = fast_tanh(fmaf(r, h_n, i_n));
                    int row = mrow + mi * 16 + hf * 8;
                    size_t idx = (size_t)row * Hh + j;
                    float hold = h_in[idx];
                    float hnew = fmaf(z, hold - nn, nn);
                    if (!odd) h_out[idx] = hnew;
                    else if (write_a2) Aout[idx] = __float2half_rn(hnew);
                }
            }
        }
    } else if (blockIdx.x < 8) {
        // ======== op head CTAs ========
        float p[8][5];
#pragma unroll
        for (int ri = 0; ri < 8; ri++)
#pragma unroll
            for (int q = 0; q < 5; q++) p[ri][q] = 0.0f;
#pragma unroll
        for (int ni = 0; ni < 4; ni++) {
            int col = cbase + ni * 8;
            float b0 = g_hb[col], b1 = g_hb[col + 1];
            float w0[5], w1[5];
#pragma unroll
            for (int q = 0; q < 5; q++) {
                w0[q] = g_Wop2t[q * Hh + col];
                w1[q] = g_Wop2t[q * Hh + col + 1];
            }
#pragma unroll
            for (int mi = 0; mi < 4; mi++) {
#pragma unroll
                for (int hf = 0; hf < 2; hf++) {
                    float a0 = gelu_exact(cc[mi][ni][hf * 2 + 0] + b0);
                    float a1 = gelu_exact(cc[mi][ni][hf * 2 + 1] + b1);
                    int ri = mi * 2 + hf;
#pragma unroll
                    for (int q = 0; q < 5; q++)
                        p[ri][q] += a0 * w0[q] + a1 * w1[q];
                }
            }
        }
#pragma unroll
        for (int ri = 0; ri < 8; ri++)
#pragma unroll
            for (int q = 0; q < 5; q++) {
                p[ri][q] += __shfl_xor_sync(0xffffffffu, p[ri][q], 1);
                p[ri][q] += __shfl_xor_sync(0xffffffffu, p[ri][q], 2);
            }
        if ((lane & 3) == 0) {
#pragma unroll
            for (int ri = 0; ri < 8; ri++) {
                int row = mrow + (ri >> 1) * 16 + (ri & 1) * 8;
#pragma unroll
                for (int q = 0; q < 5; q++)
                    atomicAdd(&ops[(size_t)row * 5 + q], p[ri][q]);
            }
        }
    } else {
        // ======== num head CTAs ========
        float pn[8];
#pragma unroll
        for (int ri = 0; ri < 8; ri++) pn[ri] = 0.0f;
#pragma unroll
        for (int ni = 0; ni < 4; ni++) {
            int col = cbase + ni * 8;
            float b0 = g_hb[col], b1 = g_hb[col + 1];
            float w0 = w_num2[col - 1024], w1 = w_num2[col - 1024 + 1];
#pragma unroll
            for (int mi = 0; mi < 4; mi++) {
#pragma unroll
                for (int hf = 0; hf < 2; hf++) {
                    float a0 = gelu_exact(cc[mi][ni][hf * 2 + 0] + b0);
                    float a1 = gelu_exact(cc[mi][ni][hf * 2 + 1] + b1);
                    pn[mi * 2 + hf] += a0 * w0 + a1 * w1;
                }
            }
        }
#pragma unroll
        for (int ri = 0; ri < 8; ri++) {
            pn[ri] += __shfl_xor_sync(0xffffffffu, pn[ri], 1);
            pn[ri] += __shfl_xor_sync(0xffffffffu, pn[ri], 2);
        }
        if ((lane & 3) == 0) {
#pragma unroll
            for (int ri = 0; ri < 8; ri++) {
                int row = mrow + (ri >> 1) * 16 + (ri & 1) * 8;
                atomicAdd(&nums[row], pn[ri]);
            }
        }
    }
}

// ---------------------------------------------------------------------------
// Launch
// ---------------------------------------------------------------------------
extern "C" void kernel_launch(void* const* d_in, const int* in_sizes, int n_in,
                              void* d_out, int out_size) {
    const float* x      = (const float*)d_in[0];
    const float* w_op1  = (const float*)d_in[2];
    const float* b_op1  = (const float*)d_in[3];
    const float* w_op2  = (const float*)d_in[4];
    const float* b_op2  = (const float*)d_in[5];
    const float* w_num1 = (const float*)d_in[6];
    const float* b_num1 = (const float*)d_in[7];
    const float* w_num2 = (const float*)d_in[8];
    const float* b_num2 = (const float*)d_in[9];
    const float* w_ih   = (const float*)d_in[10];
    const float* b_ih   = (const float*)d_in[11];
    const float* w_hh   = (const float*)d_in[12];
    const float* b_hh   = (const float*)d_in[13];

    float* out = (float*)d_out;
    float* final_state = out;
    float* ops    = out + (size_t)Bb * Hh;
    float* nums   = ops + (size_t)Ss * Bb * 5;
    float* states = nums + (size_t)Ss * Bb;

    static bool attr_set = false;
    if (!attr_set) {
        cudaFuncSetAttribute(gemm_fused, cudaFuncAttributeMaxDynamicSharedMemorySize, SMEM_TOT);
        attr_set = true;
    }

    pack_w2<<<(NW * 1024) / 256, 256>>>(w_op1, w_num1, w_ih, w_hh);
    pack_misc<<<44, 256>>>(w_op2, b_op1, b_num1, b_ih, b_hh);
    convert_x<<<(Bb * Hh) / 256, 256>>>(x, states);
    init_heads_all<<<(Ss * Bb * 6) / 256, 256>>>(ops, nums, b_op2, b_num2);

    __half* a2base = nullptr;
    cudaGetSymbolAddress((void**)&a2base, g_A2);

    for (int s = 0; s < Ss; s++) {
        float* ops_s  = ops + (size_t)s * Bb * 5;
        float* nums_s = nums + (size_t)s * Bb;

        const __half* Ain = a2base + (size_t)(s & 1) * Bb * KTOT;
        __half* Aout      = a2base + (size_t)((s + 1) & 1) * Bb * KTOT;
        const float* h    = states + (size_t)s * Bb * Hh;
        float* h_out = (s == Ss - 1) ? final_state
                                     : states + (size_t)(s + 1) * Bb * Hh;

        dim3 ggrid(NW / BN, Bb / BM);   // (48, 128)
        gemm_fused<<<ggrid, NTHREADS, SMEM_TOT>>>(Ain, Aout, h, h_out, w_num2,
                                                  ops_s, nums_s, (s == Ss - 1) ? 0 : 1);
    }
}

// round 15
// speedup vs baseline: 1.3471x; 1.3471x over previous
#include <cuda_runtime.h>
#include <cuda_fp16.h>
#include <cstdint>
#include <cstddef>

// Problem constants
#define Hh   1024
#define Bb   16384
#define Ss   8
#define NW   6144          // [op1 | num1 | gates interleaved 4*j+g]
#define KTOT 1024
#define NCHUNK 16          // KTOT / 64

#define BM 128
#define BN 128
#define STAGES      3
#define STAGE_BYTES 32768  // A 128x64 fp16 (16KB) + B 128x64 fp16 (16KB)
#define SMEM_TOT    (STAGES * STAGE_BYTES)
#define NTHREADS    256

// ---------------------------------------------------------------------------
// Device scratch
// ---------------------------------------------------------------------------
__device__ __half  g_W2[(size_t)NW * KTOT];      // 12.6 MB packed fp16 weights
__device__ __half  g_A2[2][(size_t)Bb * KTOT];   // ping-pong fp16 activations
__device__ float   g_Wop2t[5 * Hh];              // transposed op head weights
__device__ float   g_hb[2 * Hh];                 // [b_op1 | b_num1]
__device__ float   g_gb[4 * Hh];                 // interleaved gate biases

// ---------------------------------------------------------------------------
// Helpers
// ---------------------------------------------------------------------------
__device__ __forceinline__ float gelu_exact(float x) {
    return 0.5f * x * (1.0f + erff(x * 0.70710678118654752f));
}
__device__ __forceinline__ float fast_sig(float x) {
    return __fdividef(1.0f, 1.0f + __expf(-x));
}
__device__ __forceinline__ float fast_tanh(float x) {
    return __fdividef(2.0f, 1.0f + __expf(-2.0f * x)) - 1.0f;
}
__device__ __forceinline__ uint32_t smem_u32(const void* p) {
    uint32_t a;
    asm("{ .reg .u64 t; cvta.to.shared.u64 t, %1; cvt.u32.u64 %0, t; }" : "=r"(a) : "l"(p));
    return a;
}
__device__ __forceinline__ void cpasync16(uint32_t dst, const void* src) {
    asm volatile("cp.async.cg.shared.global [%0], [%1], 16;" :: "r"(dst), "l"(src) : "memory");
}
__device__ __forceinline__ void cp_commit() {
    asm volatile("cp.async.commit_group;" ::: "memory");
}
template <int N>
__device__ __forceinline__ void cp_wait() {
    asm volatile("cp.async.wait_group %0;" :: "n"(N) : "memory");
}
__device__ __forceinline__ void ldsm4(uint32_t* r, uint32_t addr) {
    asm volatile("ldmatrix.sync.aligned.m8n8.x4.shared.b16 {%0,%1,%2,%3}, [%4];"
                 : "=r"(r[0]), "=r"(r[1]), "=r"(r[2]), "=r"(r[3]) : "r"(addr));
}
__device__ __forceinline__ void mma_f16(float* c, const uint32_t* a, const uint32_t* b) {
    asm volatile(
        "mma.sync.aligned.m16n8k16.row.col.f32.f16.f16.f32 "
        "{%0,%1,%2,%3}, {%4,%5,%6,%7}, {%8,%9}, {%0,%1,%2,%3};"
        : "+f"(c[0]), "+f"(c[1]), "+f"(c[2]), "+f"(c[3])
        : "r"(a[0]), "r"(a[1]), "r"(a[2]), "r"(a[3]), "r"(b[0]), "r"(b[1]));
}
__device__ __forceinline__ uint32_t sw128(uint32_t off) {
    return off ^ ((off >> 3) & 0x70);
}

// ---------------------------------------------------------------------------
// Pack fp16 weights, gate-interleaved:
//   n<1024: op1^T; n<2048: num1^T;
//   n>=2048: j=(n-2048)>>2, g=n&3: [r_comb | z_comb | i_n | h_n]
// ---------------------------------------------------------------------------
__global__ void pack_w2(const float* __restrict__ w_op1, const float* __restrict__ w_num1,
                        const float* __restrict__ w_ih, const float* __restrict__ w_hh) {
    size_t idx = (size_t)blockIdx.x * 256 + threadIdx.x;   // over NW*1024
    int n = (int)(idx >> 10);
    int kk = (int)(idx & 1023);
    float v;
    if (n < 1024)      v = w_op1[(size_t)kk * Hh + n];
    else if (n < 2048) v = w_num1[(size_t)kk * Hh + (n - 1024)];
    else {
        int j = (n - 2048) >> 2;
        int g = n & 3;
        if (g == 0)      v = w_ih[(size_t)j * Hh + kk] + w_hh[(size_t)j * Hh + kk];
        else if (g == 1) v = w_ih[(size_t)(1024 + j) * Hh + kk] + w_hh[(size_t)(1024 + j) * Hh + kk];
        else if (g == 2) v = w_ih[(size_t)(2048 + j) * Hh + kk];
        else             v = w_hh[(size_t)(2048 + j) * Hh + kk];
    }
    g_W2[idx] = __float2half_rn(v);
}

__global__ void pack_misc(const float* __restrict__ w_op2,
                          const float* __restrict__ b_op1, const float* __restrict__ b_num1,
                          const float* __restrict__ b_ih, const float* __restrict__ b_hh) {
    int idx = blockIdx.x * 256 + threadIdx.x;   // 0..11263
    if (idx < 5120) {
        int q = idx >> 10, c = idx & 1023;
        g_Wop2t[idx] = w_op2[(size_t)c * 5 + q];
    } else if (idx < 5120 + 2048) {
        int c = idx - 5120;
        g_hb[c] = (c < 1024) ? b_op1[c] : b_num1[c - 1024];
    } else if (idx < 5120 + 2048 + 4096) {
        int c = idx - 5120 - 2048;
        int j = c >> 2, g = c & 3;
        float v;
        if (g == 0)      v = b_ih[j] + b_hh[j];
        else if (g == 1) v = b_ih[1024 + j] + b_hh[1024 + j];
        else if (g == 2) v = b_ih[2048 + j];
        else             v = b_hh[2048 + j];
        g_gb[c] = v;
    }
}

__global__ void convert_x(const float* __restrict__ x, float* __restrict__ states0) {
    size_t idx = (size_t)blockIdx.x * 256 + threadIdx.x;
    float h = x[idx];
    states0[idx] = h;
    g_A2[0][idx] = __float2half_rn(h);
}

// init ALL steps' ops/nums with biases (one launch, replaces 8 per-step inits)
__global__ void init_heads_all(float* __restrict__ ops, float* __restrict__ nums,
                               const float* __restrict__ b_op2, const float* __restrict__ b_num2) {
    int idx = blockIdx.x * 256 + threadIdx.x;   // 0 .. Ss*Bb*6-1
    int tot_ops = Ss * Bb * 5;
    if (idx < tot_ops) ops[idx] = b_op2[idx % 5];
    else if (idx < tot_ops + Ss * Bb) nums[idx - tot_ops] = b_num2[0];
}

// ---------------------------------------------------------------------------
// Fused HMMA GEMM + heads/GRU epilogue (R10 champion configuration).
// BM=128, BN=128, BK=64. 256 threads = 8 warps (2 m x 4 n), warp tile 64x32.
// 3-stage cp.async pipeline, 2 CTAs/SM for bubble overlap.
// n-blocks: [0,8): op head; [8,16): num head; [16,48): gates.
// ---------------------------------------------------------------------------
__global__ void __launch_bounds__(NTHREADS, 2)
gemm_fused(const __half* __restrict__ Ain, __half* __restrict__ Aout,
           const float* __restrict__ h_in, float* __restrict__ h_out,
           const float* __restrict__ w_num2,
           float* __restrict__ ops, float* __restrict__ nums, int write_a2) {
    extern __shared__ char smem[];
    uint32_t sb = smem_u32(smem);
    int tid = threadIdx.x;
    int lane = tid & 31;
    int wid = tid >> 5;
    int n0 = blockIdx.x * BN;
    int m0 = blockIdx.y * BM;

    // ---- cp.async bases: 8 segs/thread (4 A + 4 B), strided by 32 rows ----
    int lrow = tid >> 3;            // 0..31
    int ls8 = tid & 7;
    uint32_t d0 = sw128((uint32_t)lrow * 128 + ls8 * 16);
    const char* pA0 = (const char*)(Ain + (size_t)(m0 + lrow) * KTOT) + ls8 * 16;
    const char* pB0 = (const char*)(g_W2 + (size_t)(n0 + lrow) * KTOT) + ls8 * 16;

    // ---- ldmatrix base offsets (ks=0); sw(off ^ ks*32) ----
    int wm = (wid >> 2) * 64;       // 0 or 64
    int wn = (wid & 3) * 32;        // 0..96
    uint32_t aoffb[4], boffb[2];
#pragma unroll
    for (int mi = 0; mi < 4; mi++)
        aoffb[mi] = sw128((uint32_t)(wm + mi * 16 + (lane & 15)) * 128 + ((lane >> 4) << 4));
#pragma unroll
    for (int nb = 0; nb < 2; nb++) {
        uint32_t rown = wn + nb * 16 + ((lane >> 4) & 1) * 8 + (lane & 7);
        boffb[nb] = sw128(rown * 128 + ((lane >> 3) & 1) * 16);
    }

    float cc[4][4][4];
#pragma unroll
    for (int mi = 0; mi < 4; mi++)
#pragma unroll
        for (int ni = 0; ni < 4; ni++)
#pragma unroll
            for (int q = 0; q < 4; q++) cc[mi][ni][q] = 0.0f;

    auto load_stage = [&](int st, int c) {
        uint32_t stb = sb + st * STAGE_BYTES;
        int kb = c * 128;
#pragma unroll
        for (int i = 0; i < 4; i++)
            cpasync16(stb + d0 + 4096 * i, pA0 + (size_t)i * 32 * (KTOT * 2) + kb);
#pragma unroll
        for (int i = 0; i < 4; i++)
            cpasync16(stb + 16384 + d0 + 4096 * i, pB0 + (size_t)i * 32 * (KTOT * 2) + kb);
    };

    // ---- prologue: 2 stages in flight ----
    load_stage(0, 0);
    cp_commit();
    load_stage(1, 1);
    cp_commit();

    // ---- main loop: one barrier per chunk ----
#pragma unroll 1
    for (int c = 0; c < NCHUNK; c++) {
        cp_wait<1>();
        __syncthreads();
        int s_ld = (c + 2) % STAGES;
        if (c + 2 < NCHUNK) load_stage(s_ld, c + 2);
        cp_commit();

        uint32_t stb = sb + (c % STAGES) * STAGE_BYTES;
#pragma unroll
        for (int ks = 0; ks < 4; ks++) {
            uint32_t kx = (uint32_t)ks * 32;
            uint32_t a[4][4];
#pragma unroll
            for (int mi = 0; mi < 4; mi++) ldsm4(a[mi], stb + (aoffb[mi] ^ kx));
            uint32_t b[4][2];
#pragma unroll
            for (int nb = 0; nb < 2; nb++) {
                uint32_t r[4];
                ldsm4(r, stb + 16384 + (boffb[nb] ^ kx));
                b[nb * 2][0] = r[0]; b[nb * 2][1] = r[1];
                b[nb * 2 + 1][0] = r[2]; b[nb * 2 + 1][1] = r[3];
            }
#pragma unroll
            for (int mi = 0; mi < 4; mi++)
#pragma unroll
                for (int ni = 0; ni < 4; ni++)
                    mma_f16(cc[mi][ni], a[mi], b[ni]);
        }
    }

    // ---- fused epilogue (R10 exact) ----
    int mrow = m0 + wm + (lane >> 2);
    int cbase = n0 + wn + (lane & 3) * 2;

    if (blockIdx.x >= 16) {
        // ======== gate CTAs: GRU combine ========
        int odd = lane & 1;
#pragma unroll
        for (int ni = 0; ni < 4; ni++) {
            int col = cbase + ni * 8;
            int j = (col - 2048) >> 2;
            float b0 = g_gb[col - 2048];
            float b1 = g_gb[col - 2048 + 1];
#pragma unroll
            for (int mi = 0; mi < 4; mi++) {
#pragma unroll
                for (int hf = 0; hf < 2; hf++) {
                    float v0 = cc[mi][ni][hf * 2 + 0] + b0;
                    float v1 = cc[mi][ni][hf * 2 + 1] + b1;
                    float u0 = __shfl_xor_sync(0xffffffffu, v0, 1);
                    float u1 = __shfl_xor_sync(0xffffffffu, v1, 1);
                    float pre_r = odd ? u0 : v0;
                    float pre_z = odd ? u1 : v1;
                    float i_n   = odd ? v0 : u0;
                    float h_n   = odd ? v1 : u1;
                    float r = fast_sig(pre_r);
                    float z = fast_sig(pre_z);
                    float nn = fast_tanh(fmaf(r, h_n, i_n));
                    int row = mrow + mi * 16 + hf * 8;
                    size_t idx = (size_t)row * Hh + j;
                    float hold = h_in[idx];
                    float hnew = fmaf(z, hold - nn, nn);
                    if (!odd) h_out[idx] = hnew;
                    else if (write_a2) Aout[idx] = __float2half_rn(hnew);
                }
            }
        }
    } else if (blockIdx.x < 8) {
        // ======== op head CTAs ========
        float p[8][5];
#pragma unroll
        for (int ri = 0; ri < 8; ri++)
#pragma unroll
            for (int q = 0; q < 5; q++) p[ri][q] = 0.0f;
#pragma unroll
        for (int ni = 0; ni < 4; ni++) {
            int col = cbase + ni * 8;
            float b0 = g_hb[col], b1 = g_hb[col + 1];
            float w0[5], w1[5];
#pragma unroll
            for (int q = 0; q < 5; q++) {
                w0[q] = g_Wop2t[q * Hh + col];
                w1[q] = g_Wop2t[q * Hh + col + 1];
            }
#pragma unroll
            for (int mi = 0; mi < 4; mi++) {
#pragma unroll
                for (int hf = 0; hf < 2; hf++) {
                    float a0 = gelu_exact(cc[mi][ni][hf * 2 + 0] + b0);
                    float a1 = gelu_exact(cc[mi][ni][hf * 2 + 1] + b1);
                    int ri = mi * 2 + hf;
#pragma unroll
                    for (int q = 0; q < 5; q++)
                        p[ri][q] += a0 * w0[q] + a1 * w1[q];
                }
            }
        }
#pragma unroll
        for (int ri = 0; ri < 8; ri++)
#pragma unroll
            for (int q = 0; q < 5; q++) {
                p[ri][q] += __shfl_xor_sync(0xffffffffu, p[ri][q], 1);
                p[ri][q] += __shfl_xor_sync(0xffffffffu, p[ri][q], 2);
            }
        if ((lane & 3) == 0) {
#pragma unroll
            for (int ri = 0; ri < 8; ri++) {
                int row = mrow + (ri >> 1) * 16 + (ri & 1) * 8;
#pragma unroll
                for (int q = 0; q < 5; q++)
                    atomicAdd(&ops[(size_t)row * 5 + q], p[ri][q]);
            }
        }
    } else {
        // ======== num head CTAs ========
        float pn[8];
#pragma unroll
        for (int ri = 0; ri < 8; ri++) pn[ri] = 0.0f;
#pragma unroll
        for (int ni = 0; ni < 4; ni++) {
            int col = cbase + ni * 8;
            float b0 = g_hb[col], b1 = g_hb[col + 1];
            float w0 = w_num2[col - 1024], w1 = w_num2[col - 1024 + 1];
#pragma unroll
            for (int mi = 0; mi < 4; mi++) {
#pragma unroll
                for (int hf = 0; hf < 2; hf++) {
                    float a0 = gelu_exact(cc[mi][ni][hf * 2 + 0] + b0);
                    float a1 = gelu_exact(cc[mi][ni][hf * 2 + 1] + b1);
                    pn[mi * 2 + hf] += a0 * w0 + a1 * w1;
                }
            }
        }
#pragma unroll
        for (int ri = 0; ri < 8; ri++) {
            pn[ri] += __shfl_xor_sync(0xffffffffu, pn[ri], 1);
            pn[ri] += __shfl_xor_sync(0xffffffffu, pn[ri], 2);
        }
        if ((lane & 3) == 0) {
#pragma unroll
            for (int ri = 0; ri < 8; ri++) {
                int row = mrow + (ri >> 1) * 16 + (ri & 1) * 8;
                atomicAdd(&nums[row], pn[ri]);
            }
        }
    }
}

// ---------------------------------------------------------------------------
// Launch
// ---------------------------------------------------------------------------
extern "C" void kernel_launch(void* const* d_in, const int* in_sizes, int n_in,
                              void* d_out, int out_size) {
    const float* x      = (const float*)d_in[0];
    const float* w_op1  = (const float*)d_in[2];
    const float* b_op1  = (const float*)d_in[3];
    const float* w_op2  = (const float*)d_in[4];
    const float* b_op2  = (const float*)d_in[5];
    const float* w_num1 = (const float*)d_in[6];
    const float* b_num1 = (const float*)d_in[7];
    const float* w_num2 = (const float*)d_in[8];
    const float* b_num2 = (const float*)d_in[9];
    const float* w_ih   = (const float*)d_in[10];
    const float* b_ih   = (const float*)d_in[11];
    const float* w_hh   = (const float*)d_in[12];
    const float* b_hh   = (const float*)d_in[13];

    float* out = (float*)d_out;
    float* final_state = out;
    float* ops    = out + (size_t)Bb * Hh;
    float* nums   = ops + (size_t)Ss * Bb * 5;
    float* states = nums + (size_t)Ss * Bb;

    static bool attr_set = false;
    if (!attr_set) {
        cudaFuncSetAttribute(gemm_fused, cudaFuncAttributeMaxDynamicSharedMemorySize, SMEM_TOT);
        attr_set = true;
    }

    pack_w2<<<(NW * 1024) / 256, 256>>>(w_op1, w_num1, w_ih, w_hh);
    pack_misc<<<44, 256>>>(w_op2, b_op1, b_num1, b_ih, b_hh);
    convert_x<<<(Bb * Hh) / 256, 256>>>(x, states);
    init_heads_all<<<(Ss * Bb * 6) / 256, 256>>>(ops, nums, b_op2, b_num2);

    __half* a2base = nullptr;
    cudaGetSymbolAddress((void**)&a2base, g_A2);

    for (int s = 0; s < Ss; s++) {
        float* ops_s  = ops + (size_t)s * Bb * 5;
        float* nums_s = nums + (size_t)s * Bb;

        const __half* Ain = a2base + (size_t)(s & 1) * Bb * KTOT;
        __half* Aout      = a2base + (size_t)((s + 1) & 1) * Bb * KTOT;
        const float* h    = states + (size_t)s * Bb * Hh;
        float* h_out = (s == Ss - 1) ? final_state
                                     : states + (size_t)(s + 1) * Bb * Hh;

        dim3 ggrid(NW / BN, Bb / BM);   // (48, 128)
        gemm_fused<<<ggrid, NTHREADS, SMEM_TOT>>>(Ain, Aout, h, h_out, w_num2,
                                                  ops_s, nums_s, (s == Ss - 1) ? 0 : 1);
    }
}

// round 16
// speedup vs baseline: 1.3898x; 1.0317x over previous
#include <cuda_runtime.h>
#include <cuda_fp16.h>
#include <cstdint>
#include <cstddef>

// Problem constants
#define Hh   1024
#define Bb   16384
#define Ss   8
#define NW   6144          // [op1 | num1 | gates interleaved 4*j+g]
#define KTOT 1024
#define NCHUNK 16          // KTOT / 64

#define BM 128
#define BN 128
#define STAGES      3
#define STAGE_BYTES 32768  // A 128x64 fp16 (16KB) + B 128x64 fp16 (16KB)
#define SMEM_TOT    (STAGES * STAGE_BYTES)
#define NTHREADS    256

// ---------------------------------------------------------------------------
// Device scratch
// ---------------------------------------------------------------------------
__device__ __half  g_W2[(size_t)NW * KTOT];      // 12.6 MB packed fp16 weights
__device__ __half  g_A2[3][(size_t)Bb * KTOT];   // 3-deep ring of fp16 activations
__device__ float   g_Wop2t[5 * Hh];              // transposed op head weights
__device__ float   g_hb[2 * Hh];                 // [b_op1 | b_num1]
__device__ float   g_gb[4 * Hh];                 // interleaved gate biases

// ---------------------------------------------------------------------------
// Helpers
// ---------------------------------------------------------------------------
__device__ __forceinline__ float gelu_exact(float x) {
    return 0.5f * x * (1.0f + erff(x * 0.70710678118654752f));
}
__device__ __forceinline__ float fast_sig(float x) {
    return __fdividef(1.0f, 1.0f + __expf(-x));
}
__device__ __forceinline__ float fast_tanh(float x) {
    return __fdividef(2.0f, 1.0f + __expf(-2.0f * x)) - 1.0f;
}
__device__ __forceinline__ uint32_t smem_u32(const void* p) {
    uint32_t a;
    asm("{ .reg .u64 t; cvta.to.shared.u64 t, %1; cvt.u32.u64 %0, t; }" : "=r"(a) : "l"(p));
    return a;
}
__device__ __forceinline__ void cpasync16(uint32_t dst, const void* src) {
    asm volatile("cp.async.cg.shared.global [%0], [%1], 16;" :: "r"(dst), "l"(src) : "memory");
}
__device__ __forceinline__ void cp_commit() {
    asm volatile("cp.async.commit_group;" ::: "memory");
}
template <int N>
__device__ __forceinline__ void cp_wait() {
    asm volatile("cp.async.wait_group %0;" :: "n"(N) : "memory");
}
__device__ __forceinline__ void ldsm4(uint32_t* r, uint32_t addr) {
    asm volatile("ldmatrix.sync.aligned.m8n8.x4.shared.b16 {%0,%1,%2,%3}, [%4];"
                 : "=r"(r[0]), "=r"(r[1]), "=r"(r[2]), "=r"(r[3]) : "r"(addr));
}
__device__ __forceinline__ void mma_f16(float* c, const uint32_t* a, const uint32_t* b) {
    asm volatile(
        "mma.sync.aligned.m16n8k16.row.col.f32.f16.f16.f32 "
        "{%0,%1,%2,%3}, {%4,%5,%6,%7}, {%8,%9}, {%0,%1,%2,%3};"
        : "+f"(c[0]), "+f"(c[1]), "+f"(c[2]), "+f"(c[3])
        : "r"(a[0]), "r"(a[1]), "r"(a[2]), "r"(a[3]), "r"(b[0]), "r"(b[1]));
}
__device__ __forceinline__ uint32_t sw128(uint32_t off) {
    return off ^ ((off >> 3) & 0x70);
}

// ---------------------------------------------------------------------------
// Pack gate weights (n in [2048,6144)): coalesced reads AND writes
// ---------------------------------------------------------------------------
__global__ void pack_wg(const float* __restrict__ w_ih, const float* __restrict__ w_hh) {
    size_t idx = (size_t)blockIdx.x * 256 + threadIdx.x;   // over 4096*1024
    int n = 2048 + (int)(idx >> 10);
    int kk = (int)(idx & 1023);
    int j = (n - 2048) >> 2;
    int g = n & 3;
    float v;
    if (g == 0)      v = w_ih[(size_t)j * Hh + kk] + w_hh[(size_t)j * Hh + kk];
    else if (g == 1) v = w_ih[(size_t)(1024 + j) * Hh + kk] + w_hh[(size_t)(1024 + j) * Hh + kk];
    else if (g == 2) v = w_ih[(size_t)(2048 + j) * Hh + kk];
    else             v = w_hh[(size_t)(2048 + j) * Hh + kk];
    g_W2[(size_t)n * KTOT + kk] = __float2half_rn(v);
}

// Transpose head weights (op1 -> n<1024, num1 -> n<2048) via smem tiles
__global__ void pack_wh_t(const float* __restrict__ w_op1, const float* __restrict__ w_num1) {
    __shared__ float tile[32][33];
    const float* src = (blockIdx.z == 0) ? w_op1 : w_num1;
    int m0 = blockIdx.x * 32;
    int kk0 = blockIdx.y * 32;
    int tx = threadIdx.x, ty = threadIdx.y;
    // read: kk=kk0+ty, m=m0+tx  (coalesced over m)
    tile[ty][tx] = src[(size_t)(kk0 + ty) * Hh + m0 + tx];
    __syncthreads();
    // write: n = z*1024 + m0+ty, kk=kk0+tx  (coalesced over kk)
    g_W2[(size_t)(blockIdx.z * 1024 + m0 + ty) * KTOT + kk0 + tx] = __float2half_rn(tile[tx][ty]);
}

__global__ void pack_misc(const float* __restrict__ w_op2,
                          const float* __restrict__ b_op1, const float* __restrict__ b_num1,
                          const float* __restrict__ b_ih, const float* __restrict__ b_hh) {
    int idx = blockIdx.x * 256 + threadIdx.x;   // 0..11263
    if (idx < 5120) {
        int q = idx >> 10, c = idx & 1023;
        g_Wop2t[idx] = w_op2[(size_t)c * 5 + q];
    } else if (idx < 5120 + 2048) {
        int c = idx - 5120;
        g_hb[c] = (c < 1024) ? b_op1[c] : b_num1[c - 1024];
    } else if (idx < 5120 + 2048 + 4096) {
        int c = idx - 5120 - 2048;
        int j = c >> 2, g = c & 3;
        float v;
        if (g == 0)      v = b_ih[j] + b_hh[j];
        else if (g == 1) v = b_ih[1024 + j] + b_hh[1024 + j];
        else if (g == 2) v = b_ih[2048 + j];
        else             v = b_hh[2048 + j];
        g_gb[c] = v;
    }
}

__global__ void convert_x(const float* __restrict__ x, float* __restrict__ states0) {
    size_t idx = (size_t)blockIdx.x * 256 + threadIdx.x;
    float h = x[idx];
    states0[idx] = h;
    g_A2[0][idx] = __float2half_rn(h);
}

// init ALL steps' ops/nums with biases (one launch)
__global__ void init_heads_all(float* __restrict__ ops, float* __restrict__ nums,
                               const float* __restrict__ b_op2, const float* __restrict__ b_num2) {
    int idx = blockIdx.x * 256 + threadIdx.x;   // 0 .. Ss*Bb*6-1
    int tot_ops = Ss * Bb * 5;
    if (idx < tot_ops) ops[idx] = b_op2[idx % 5];
    else if (idx < tot_ops + Ss * Bb) nums[idx - tot_ops] = b_num2[0];
}

// ---------------------------------------------------------------------------
// Shared HMMA mainloop: computes cc = A[m0:m0+128] x W2[n0:n0+128]^T
// ---------------------------------------------------------------------------
__device__ __forceinline__ void run_mainloop(const __half* __restrict__ Ain,
                                             int n0, int m0, uint32_t sb,
                                             int tid, int lane, int wid,
                                             int wm, int wn,
                                             float (&cc)[4][4][4]) {
    // ---- cp.async bases: 8 segs/thread (4 A + 4 B), strided by 32 rows ----
    int lrow = tid >> 3;            // 0..31
    int ls8 = tid & 7;
    uint32_t d0 = sw128((uint32_t)lrow * 128 + ls8 * 16);
    const char* pA0 = (const char*)(Ain + (size_t)(m0 + lrow) * KTOT) + ls8 * 16;
    const char* pB0 = (const char*)(g_W2 + (size_t)(n0 + lrow) * KTOT) + ls8 * 16;

    // ---- ldmatrix base offsets (ks=0); sw(off ^ ks*32) ----
    uint32_t aoffb[4], boffb[2];
#pragma unroll
    for (int mi = 0; mi < 4; mi++)
        aoffb[mi] = sw128((uint32_t)(wm + mi * 16 + (lane & 15)) * 128 + ((lane >> 4) << 4));
#pragma unroll
    for (int nb = 0; nb < 2; nb++) {
        uint32_t rown = wn + nb * 16 + ((lane >> 4) & 1) * 8 + (lane & 7);
        boffb[nb] = sw128(rown * 128 + ((lane >> 3) & 1) * 16);
    }

#pragma unroll
    for (int mi = 0; mi < 4; mi++)
#pragma unroll
        for (int ni = 0; ni < 4; ni++)
#pragma unroll
            for (int q = 0; q < 4; q++) cc[mi][ni][q] = 0.0f;

    auto load_stage = [&](int st, int c) {
        uint32_t stb = sb + st * STAGE_BYTES;
        int kb = c * 128;
#pragma unroll
        for (int i = 0; i < 4; i++)
            cpasync16(stb + d0 + 4096 * i, pA0 + (size_t)i * 32 * (KTOT * 2) + kb);
#pragma unroll
        for (int i = 0; i < 4; i++)
            cpasync16(stb + 16384 + d0 + 4096 * i, pB0 + (size_t)i * 32 * (KTOT * 2) + kb);
    };

    load_stage(0, 0);
    cp_commit();
    load_stage(1, 1);
    cp_commit();

#pragma unroll 1
    for (int c = 0; c < NCHUNK; c++) {
        cp_wait<1>();
        __syncthreads();
        int s_ld = (c + 2) % STAGES;
        if (c + 2 < NCHUNK) load_stage(s_ld, c + 2);
        cp_commit();

        uint32_t stb = sb + (c % STAGES) * STAGE_BYTES;
#pragma unroll
        for (int ks = 0; ks < 4; ks++) {
            uint32_t kx = (uint32_t)ks * 32;
            uint32_t a[4][4];
#pragma unroll
            for (int mi = 0; mi < 4; mi++) ldsm4(a[mi], stb + (aoffb[mi] ^ kx));
            uint32_t b[4][2];
#pragma unroll
            for (int nb = 0; nb < 2; nb++) {
                uint32_t r[4];
                ldsm4(r, stb + 16384 + (boffb[nb] ^ kx));
                b[nb * 2][0] = r[0]; b[nb * 2][1] = r[1];
                b[nb * 2 + 1][0] = r[2]; b[nb * 2 + 1][1] = r[3];
            }
#pragma unroll
            for (int mi = 0; mi < 4; mi++)
#pragma unroll
                for (int ni = 0; ni < 4; ni++)
                    mma_f16(cc[mi][ni], a[mi], b[ni]);
        }
    }
}

// ---------------------------------------------------------------------------
// Gates kernel: recurrence critical path (GEMM + GRU combine)
// grid (32, 128): n0 = 2048 + bx*128
// ---------------------------------------------------------------------------
__global__ void __launch_bounds__(NTHREADS, 2)
gemm_gates(const __half* __restrict__ Ain, __half* __restrict__ Aout,
           const float* __restrict__ h_in, float* __restrict__ h_out, int write_a2) {
    extern __shared__ char smem[];
    uint32_t sb = smem_u32(smem);
    int tid = threadIdx.x;
    int lane = tid & 31;
    int wid = tid >> 5;
    int n0 = 2048 + blockIdx.x * BN;
    int m0 = blockIdx.y * BM;
    int wm = (wid >> 2) * 64;
    int wn = (wid & 3) * 32;

    float cc[4][4][4];
    run_mainloop(Ain, n0, m0, sb, tid, lane, wid, wm, wn, cc);

    int mrow = m0 + wm + (lane >> 2);
    int cbase = n0 + wn + (lane & 3) * 2;
    int odd = lane & 1;
#pragma unroll
    for (int ni = 0; ni < 4; ni++) {
        int col = cbase + ni * 8;
        int j = (col - 2048) >> 2;
        float b0 = g_gb[col - 2048];
        float b1 = g_gb[col - 2048 + 1];
#pragma unroll
        for (int mi = 0; mi < 4; mi++) {
#pragma unroll
            for (int hf = 0; hf < 2; hf++) {
                float v0 = cc[mi][ni][hf * 2 + 0] + b0;
                float v1 = cc[mi][ni][hf * 2 + 1] + b1;
                float u0 = __shfl_xor_sync(0xffffffffu, v0, 1);
                float u1 = __shfl_xor_sync(0xffffffffu, v1, 1);
                float pre_r = odd ? u0 : v0;
                float pre_z = odd ? u1 : v1;
                float i_n   = odd ? v0 : u0;
                float h_n   = odd ? v1 : u1;
                float r = fast_sig(pre_r);
                float z = fast_sig(pre_z);
                float nn = fast_tanh(fmaf(r, h_n, i_n));
                int row = mrow + mi * 16 + hf * 8;
                size_t idx = (size_t)row * Hh + j;
                float hold = h_in[idx];
                float hnew = fmaf(z, hold - nn, nn);
                if (!odd) h_out[idx] = hnew;
                else if (write_a2) Aout[idx] = __float2half_rn(hnew);
            }
        }
    }
}

// ---------------------------------------------------------------------------
// Heads kernel: terminal outputs (GEMM + GELU + tiny matmuls -> atomics)
// grid (16, 128): bx<8 op head, bx>=8 num head; n0 = bx*128
// ---------------------------------------------------------------------------
__global__ void __launch_bounds__(NTHREADS, 2)
gemm_heads(const __half* __restrict__ Ain, const float* __restrict__ w_num2,
           float* __restrict__ ops, float* __restrict__ nums) {
    extern __shared__ char smem[];
    uint32_t sb = smem_u32(smem);
    int tid = threadIdx.x;
    int lane = tid & 31;
    int wid = tid >> 5;
    int n0 = blockIdx.x * BN;
    int m0 = blockIdx.y * BM;
    int wm = (wid >> 2) * 64;
    int wn = (wid & 3) * 32;

    float cc[4][4][4];
    run_mainloop(Ain, n0, m0, sb, tid, lane, wid, wm, wn, cc);

    int mrow = m0 + wm + (lane >> 2);
    int cbase = n0 + wn + (lane & 3) * 2;

    if (blockIdx.x < 8) {
        // ======== op head ========
        float p[8][5];
#pragma unroll
        for (int ri = 0; ri < 8; ri++)
#pragma unroll
            for (int q = 0; q < 5; q++) p[ri][q] = 0.0f;
#pragma unroll
        for (int ni = 0; ni < 4; ni++) {
            int col = cbase + ni * 8;
            float b0 = g_hb[col], b1 = g_hb[col + 1];
            float w0[5], w1[5];
#pragma unroll
            for (int q = 0; q < 5; q++) {
                w0[q] = g_Wop2t[q * Hh + col];
                w1[q] = g_Wop2t[q * Hh + col + 1];
            }
#pragma unroll
            for (int mi = 0; mi < 4; mi++) {
#pragma unroll
                for (int hf = 0; hf < 2; hf++) {
                    float a0 = gelu_exact(cc[mi][ni][hf * 2 + 0] + b0);
                    float a1 = gelu_exact(cc[mi][ni][hf * 2 + 1] + b1);
                    int ri = mi * 2 + hf;
#pragma unroll
                    for (int q = 0; q < 5; q++)
                        p[ri][q] += a0 * w0[q] + a1 * w1[q];
                }
            }
        }
#pragma unroll
        for (int ri = 0; ri < 8; ri++)
#pragma unroll
            for (int q = 0; q < 5; q++) {
                p[ri][q] += __shfl_xor_sync(0xffffffffu, p[ri][q], 1);
                p[ri][q] += __shfl_xor_sync(0xffffffffu, p[ri][q], 2);
            }
        if ((lane & 3) == 0) {
#pragma unroll
            for (int ri = 0; ri < 8; ri++) {
                int row = mrow + (ri >> 1) * 16 + (ri & 1) * 8;
#pragma unroll
                for (int q = 0; q < 5; q++)
                    atomicAdd(&ops[(size_t)row * 5 + q], p[ri][q]);
            }
        }
    } else {
        // ======== num head ========
        float pn[8];
#pragma unroll
        for (int ri = 0; ri < 8; ri++) pn[ri] = 0.0f;
#pragma unroll
        for (int ni = 0; ni < 4; ni++) {
            int col = cbase + ni * 8;
            float b0 = g_hb[col], b1 = g_hb[col + 1];
            float w0 = w_num2[col - 1024], w1 = w_num2[col - 1024 + 1];
#pragma unroll
            for (int mi = 0; mi < 4; mi++) {
#pragma unroll
                for (int hf = 0; hf < 2; hf++) {
                    float a0 = gelu_exact(cc[mi][ni][hf * 2 + 0] + b0);
                    float a1 = gelu_exact(cc[mi][ni][hf * 2 + 1] + b1);
                    pn[mi * 2 + hf] += a0 * w0 + a1 * w1;
                }
            }
        }
#pragma unroll
        for (int ri = 0; ri < 8; ri++) {
            pn[ri] += __shfl_xor_sync(0xffffffffu, pn[ri], 1);
            pn[ri] += __shfl_xor_sync(0xffffffffu, pn[ri], 2);
        }
        if ((lane & 3) == 0) {
#pragma unroll
            for (int ri = 0; ri < 8; ri++) {
                int row = mrow + (ri >> 1) * 16 + (ri & 1) * 8;
                atomicAdd(&nums[row], pn[ri]);
            }
        }
    }
}

// ---------------------------------------------------------------------------
// Launch: gates chain on stream G; heads overlapped on stream H.
// Dependencies: heads_s <- gates_{s-1} (Ain ready);
//               gates_s <- evH[s-2] (A-ring WAR, 3 buffers => 2-step slack).
// ---------------------------------------------------------------------------
extern "C" void kernel_launch(void* const* d_in, const int* in_sizes, int n_in,
                              void* d_out, int out_size) {
    const float* x      = (const float*)d_in[0];
    const float* w_op1  = (const float*)d_in[2];
    const float* b_op1  = (const float*)d_in[3];
    const float* w_op2  = (const float*)d_in[4];
    const float* b_op2  = (const float*)d_in[5];
    const float* w_num1 = (const float*)d_in[6];
    const float* b_num1 = (const float*)d_in[7];
    const float* w_num2 = (const float*)d_in[8];
    const float* b_num2 = (const float*)d_in[9];
    const float* w_ih   = (const float*)d_in[10];
    const float* b_ih   = (const float*)d_in[11];
    const float* w_hh   = (const float*)d_in[12];
    const float* b_hh   = (const float*)d_in[13];

    float* out = (float*)d_out;
    float* final_state = out;
    float* ops    = out + (size_t)Bb * Hh;
    float* nums   = ops + (size_t)Ss * Bb * 5;
    float* states = nums + (size_t)Ss * Bb;

    static cudaStream_t sG = nullptr, sH = nullptr;
    static cudaEvent_t evFork, evG[Ss], evH[Ss];
    static bool init_done = false;
    if (!init_done) {
        cudaFuncSetAttribute(gemm_gates, cudaFuncAttributeMaxDynamicSharedMemorySize, SMEM_TOT);
        cudaFuncSetAttribute(gemm_heads, cudaFuncAttributeMaxDynamicSharedMemorySize, SMEM_TOT);
        cudaStreamCreateWithFlags(&sG, cudaStreamNonBlocking);
        cudaStreamCreateWithFlags(&sH, cudaStreamNonBlocking);
        cudaEventCreateWithFlags(&evFork, cudaEventDisableTiming);
        for (int s = 0; s < Ss; s++) {
            cudaEventCreateWithFlags(&evG[s], cudaEventDisableTiming);
            cudaEventCreateWithFlags(&evH[s], cudaEventDisableTiming);
        }
        init_done = true;
    }

    __half* a2base = nullptr;
    cudaGetSymbolAddress((void**)&a2base, g_A2);
    const size_t ABUF = (size_t)Bb * KTOT;

    // ---- prep on the capture (legacy) stream ----
    pack_wg<<<(4096 * 1024) / 256, 256>>>(w_ih, w_hh);
    pack_wh_t<<<dim3(32, 32, 2), dim3(32, 32)>>>(w_op1, w_num1);
    pack_misc<<<44, 256>>>(w_op2, b_op1, b_num1, b_ih, b_hh);
    convert_x<<<(Bb * Hh) / 256, 256>>>(x, states);
    init_heads_all<<<(Ss * Bb * 6) / 256, 256>>>(ops, nums, b_op2, b_num2);

    // ---- fork ----
    cudaEventRecord(evFork, 0);
    cudaStreamWaitEvent(sG, evFork, 0);
    cudaStreamWaitEvent(sH, evFork, 0);

    for (int s = 0; s < Ss; s++) {
        const __half* Ain = a2base + (size_t)(s % 3) * ABUF;
        __half* Aout      = a2base + (size_t)((s + 1) % 3) * ABUF;
        const float* h    = states + (size_t)s * Bb * Hh;
        float* h_out = (s == Ss - 1) ? final_state
                                     : states + (size_t)(s + 1) * Bb * Hh;

        // gates (critical path): WAR guard against heads two steps back
        if (s >= 2) cudaStreamWaitEvent(sG, evH[s - 2], 0);
        gemm_gates<<<dim3(32, 128), NTHREADS, SMEM_TOT, sG>>>(
            Ain, Aout, h, h_out, (s == Ss - 1) ? 0 : 1);
        cudaEventRecord(evG[s], sG);

        // heads (off critical path): needs Ain of step s
        if (s > 0) cudaStreamWaitEvent(sH, evG[s - 1], 0);
        gemm_heads<<<dim3(16, 128), NTHREADS, SMEM_TOT, sH>>>(
            Ain, w_num2, ops + (size_t)s * Bb * 5, nums + (size_t)s * Bb);
        cudaEventRecord(evH[s], sH);
    }

    // ---- join back onto the capture stream ----
    cudaStreamWaitEvent(0, evG[Ss - 1], 0);
    cudaStreamWaitEvent(0, evH[Ss - 1], 0);
}